// round 8
// baseline (speedup 1.0000x reference)
#include <cuda_runtime.h>
#include <cstdint>

#define T_LEN 16384
#define NXD 128
#define NHD 512
#define STEPS (T_LEN - NXD)   /* 16256 */
#define NGC (NHD * 4)         /* 2048 */

// h history: per (t,j) one u64 = (tag = t+1) << 32 | float bits of h
__device__ unsigned long long g_h64[(size_t)STEPS * NHD];   // 66 MB
// gate pre-activations, interleaved (f,i,o,c) per (t,j)
__device__ float4 g_gate4[(size_t)STEPS * NHD];             // 133 MB

__device__ __forceinline__ void ld_rlx2(const unsigned long long* p,
                                        unsigned long long& a, unsigned long long& b) {
    asm volatile("ld.relaxed.gpu.global.v2.u64 {%0,%1}, [%2];"
                 : "=l"(a), "=l"(b) : "l"(p) : "memory");
}
__device__ __forceinline__ void st_rlx(unsigned long long* p, unsigned long long v) {
    asm volatile("st.relaxed.gpu.global.u64 [%0], %1;" :: "l"(p), "l"(v) : "memory");
}
__device__ __forceinline__ void st_rel_cta(unsigned* p, unsigned v) {
    asm volatile("st.release.cta.u32 [%0], %1;" :: "l"(p), "r"(v) : "memory");
}
__device__ __forceinline__ unsigned ld_acq_cta(const unsigned* p) {
    unsigned v;
    asm volatile("ld.acquire.cta.u32 %0, [%1];" : "=r"(v) : "l"(p) : "memory");
    return v;
}
__device__ __forceinline__ float tanh_hw(float x) {
    float y;
    asm("tanh.approx.f32 %0, %1;" : "=f"(y) : "f"(x));
    return y;
}
__device__ __forceinline__ float sigm(float x) {
    return fmaf(tanh_hw(0.5f * x), 0.5f, 0.5f);
}
__device__ __forceinline__ float dot4(float4 a, float4 b) {
    return a.x * b.x + a.y * b.y + a.z * b.z + a.w * b.w;
}
__device__ __forceinline__ float lo_f(unsigned long long v) {
    return __uint_as_float((unsigned)v);
}

// ---------------------------------------------------------------------------
// Clear tags (END of each call; device globals are zero-init for call 1)
// ---------------------------------------------------------------------------
__global__ void zero_kernel() {
    int idx = blockIdx.x * blockDim.x + threadIdx.x;
    int stride = gridDim.x * blockDim.x;
    for (int i = idx; i < STEPS * NHD; i += stride) g_h64[i] = 0ull;
}

// ---------------------------------------------------------------------------
// Gate pre-activation GEMM: gate[t][c] = b + sum_k W[c][k] * x[t+k]
// ---------------------------------------------------------------------------
__global__ void precompute_kernel(const float* __restrict__ x,
                                  const float* __restrict__ Wf, const float* __restrict__ bf,
                                  const float* __restrict__ Wi, const float* __restrict__ bi,
                                  const float* __restrict__ Wo, const float* __restrict__ bo,
                                  const float* __restrict__ Wc, const float* __restrict__ bc) {
    __shared__ float xs[192];
    __shared__ float Ws[128][65];
    const int tBase = blockIdx.x * 64;
    const int cBase = blockIdx.y * 64;
    const int tid = threadIdx.x;

    for (int i = tid; i < 191; i += 256) xs[i] = x[tBase + i];
    for (int idx = tid; idx < 8192; idx += 256) {
        int r = idx >> 7, k = idx & 127;
        int c = cBase + r;
        int j = c >> 2, g = c & 3;
        const float* W = (g == 0) ? Wf : (g == 1) ? Wi : (g == 2) ? Wo : Wc;
        Ws[k][r] = W[j * NXD + k];
    }
    __syncthreads();

    const int tx = tid & 15, ty = tid >> 4;
    const int t0 = ty * 4, r0 = tx * 4;
    float acc[4][4] = {};
#pragma unroll 4
    for (int k = 0; k < 128; k++) {
        float a0 = xs[t0 + 0 + k], a1 = xs[t0 + 1 + k];
        float a2 = xs[t0 + 2 + k], a3 = xs[t0 + 3 + k];
        float b0 = Ws[k][r0 + 0], b1 = Ws[k][r0 + 1];
        float b2 = Ws[k][r0 + 2], b3 = Ws[k][r0 + 3];
        acc[0][0] += a0 * b0; acc[0][1] += a0 * b1; acc[0][2] += a0 * b2; acc[0][3] += a0 * b3;
        acc[1][0] += a1 * b0; acc[1][1] += a1 * b1; acc[1][2] += a1 * b2; acc[1][3] += a1 * b3;
        acc[2][0] += a2 * b0; acc[2][1] += a2 * b1; acc[2][2] += a2 * b2; acc[2][3] += a2 * b3;
        acc[3][0] += a3 * b0; acc[3][1] += a3 * b1; acc[3][2] += a3 * b2; acc[3][3] += a3 * b3;
    }
    float* out = reinterpret_cast<float*>(g_gate4);
#pragma unroll
    for (int ti = 0; ti < 4; ti++) {
#pragma unroll
        for (int cj = 0; cj < 4; cj++) {
            int t = tBase + t0 + ti;
            int c = cBase + r0 + cj;
            int j = c >> 2, g = c & 3;
            float bias = (g == 0) ? bf[j] : (g == 1) ? bi[j] : (g == 2) ? bo[j] : bc[j];
            out[(size_t)t * NGC + c] = acc[ti][cj] + bias;
        }
    }
}

// ---------------------------------------------------------------------------
// Persistent self-synchronizing recurrence with WATCHER warps.
// 128 CTAs x 192 threads (warps 0-3 compute, warps 4-5 watchers).
// Warp w (<4) owns output j = 4b + w; exchange format/compute/epilogue are
// exactly the proven R2 shape (tagged u64, strided reads, lane-0 epilogue).
// Watcher warp 4+half polls slots [half*256, half*256+256) (8 slots/lane via
// 4x ld.relaxed.v2.u64, independent retry), converts fresh values into the
// smem double buffer, then publishes flags[half]=t via st.release.cta.
// Compute warps spin on the two flags via ld.acquire.cta -- NO __syncthreads
// on the chain, no compute-warp global polling.
//
// Buffer-overwrite safety: watcher writes buffer (tt+1)&1 for row tt+1 only
// after some CTA produced row tt+1; producing row tt+1 requires ALL of row
// tt, i.e. every warp's step-tt store, which (per-warp program order) is
// preceded by that warp's buffer reads for step tt. So all step-tt reads of
// buffer (tt-1)&1 == (tt+1)&1 complete before any row-tt+1 data can arrive.
// ---------------------------------------------------------------------------
__global__ void __launch_bounds__(192, 1)
lstm_rec_kernel(const float* __restrict__ Uf, const float* __restrict__ Ui,
                const float* __restrict__ Uo, const float* __restrict__ Uc) {
    __shared__ float hs[2][NHD];
    __shared__ unsigned flags[2];

    const int tid = threadIdx.x;
    const int w = tid >> 5, l = tid & 31;

    if (tid < 2) flags[tid] = 0u;
    __syncthreads();   // once, before the loop

    if (w >= 4) {
        // ---------------- watcher warp ----------------
        const int half = w - 4;
        const int base = half * 256 + l * 8;
        for (int tt = 0; tt < STEPS - 1; tt++) {
            const unsigned long long* src = g_h64 + (size_t)tt * NHD + base;
            float* dst = hs[tt & 1] + base;
            const unsigned tag = (unsigned)(tt + 1);
            bool d0 = false, d1 = false, d2 = false, d3 = false;
            unsigned long long a, b;
            do {
                if (!d0) {
                    ld_rlx2(src + 0, a, b);
                    if (((unsigned)(a >> 32) == tag) & ((unsigned)(b >> 32) == tag)) {
                        dst[0] = lo_f(a); dst[1] = lo_f(b); d0 = true;
                    }
                }
                if (!d1) {
                    ld_rlx2(src + 2, a, b);
                    if (((unsigned)(a >> 32) == tag) & ((unsigned)(b >> 32) == tag)) {
                        dst[2] = lo_f(a); dst[3] = lo_f(b); d1 = true;
                    }
                }
                if (!d2) {
                    ld_rlx2(src + 4, a, b);
                    if (((unsigned)(a >> 32) == tag) & ((unsigned)(b >> 32) == tag)) {
                        dst[4] = lo_f(a); dst[5] = lo_f(b); d2 = true;
                    }
                }
                if (!d3) {
                    ld_rlx2(src + 6, a, b);
                    if (((unsigned)(a >> 32) == tag) & ((unsigned)(b >> 32) == tag)) {
                        dst[6] = lo_f(a); dst[7] = lo_f(b); d3 = true;
                    }
                }
            } while (!(d0 & d1 & d2 & d3));
            __syncwarp(0xffffffffu);
            if (l == 0) st_rel_cta(&flags[half], tag);
        }
        return;
    }

    // ---------------- compute warp (R2 body) ----------------
    const int j = blockIdx.x * 4 + w;

    float4 u[4][4];
#pragma unroll
    for (int m = 0; m < 4; m++) {
        int off = j * NHD + m * 128 + l * 4;
        u[0][m] = *reinterpret_cast<const float4*>(Uf + off);
        u[1][m] = *reinterpret_cast<const float4*>(Ui + off);
        u[2][m] = *reinterpret_cast<const float4*>(Uo + off);
        u[3][m] = *reinterpret_cast<const float4*>(Uc + off);
    }

    float cst = 0.f;
    float4 gx = make_float4(0.f, 0.f, 0.f, 0.f);
    if (l == 0) gx = g_gate4[j];   // gate inputs for t = 0

    for (int t = 0; t < STEPS; t++) {
        float4 h0, h1, h2, h3;
        if (t == 0) {
            h0 = h1 = h2 = h3 = make_float4(0.f, 0.f, 0.f, 0.f);
        } else {
            const unsigned tt = (unsigned)t;
            while (ld_acq_cta(&flags[0]) < tt) {}
            while (ld_acq_cta(&flags[1]) < tt) {}
            const float* hb = hs[(t - 1) & 1];
            h0 = *reinterpret_cast<const float4*>(hb + 0   + l * 4);
            h1 = *reinterpret_cast<const float4*>(hb + 128 + l * 4);
            h2 = *reinterpret_cast<const float4*>(hb + 256 + l * 4);
            h3 = *reinterpret_cast<const float4*>(hb + 384 + l * 4);
        }

        float a0 = dot4(u[0][0], h0) + dot4(u[0][1], h1) + dot4(u[0][2], h2) + dot4(u[0][3], h3);
        float a1 = dot4(u[1][0], h0) + dot4(u[1][1], h1) + dot4(u[1][2], h2) + dot4(u[1][3], h3);
        float a2 = dot4(u[2][0], h0) + dot4(u[2][1], h1) + dot4(u[2][2], h2) + dot4(u[2][3], h3);
        float a3 = dot4(u[3][0], h0) + dot4(u[3][1], h1) + dot4(u[3][2], h2) + dot4(u[3][3], h3);

#pragma unroll
        for (int off = 16; off; off >>= 1) {
            a0 += __shfl_down_sync(0xffffffffu, a0, off);
            a1 += __shfl_down_sync(0xffffffffu, a1, off);
            a2 += __shfl_down_sync(0xffffffffu, a2, off);
            a3 += __shfl_down_sync(0xffffffffu, a3, off);
        }

        if (l == 0) {
            float f = sigm(gx.x + a0);
            float i = sigm(gx.y + a1);
            float o = sigm(gx.z + a2);
            float g = tanh_hw(gx.w + a3);
            cst = f * cst + i * g;
            float h = o * tanh_hw(cst);
            st_rlx(g_h64 + (size_t)t * NHD + j,
                   ((unsigned long long)(unsigned)(t + 1) << 32) |
                   (unsigned long long)__float_as_uint(h));
            if (t + 1 < STEPS) gx = g_gate4[(size_t)(t + 1) * NHD + j];  // prefetch
        }
    }
}

// ---------------------------------------------------------------------------
// mu epilogue: out[t] = by + sum_j Ahy[j] * h[t][j]   (one warp per t)
// ---------------------------------------------------------------------------
__global__ void mu_kernel(const float* __restrict__ Ahy, const float* __restrict__ by,
                          float* __restrict__ out) {
    int gw = (int)((blockIdx.x * blockDim.x + threadIdx.x) >> 5);
    int l = threadIdx.x & 31;
    if (gw >= STEPS) return;
    const unsigned long long* hrow = g_h64 + (size_t)gw * NHD;
    float s = 0.f;
#pragma unroll
    for (int m = 0; m < 16; m++) {
        int idx = l + 32 * m;
        s += Ahy[idx] * __uint_as_float((unsigned)hrow[idx]);
    }
#pragma unroll
    for (int off = 16; off; off >>= 1) s += __shfl_down_sync(0xffffffffu, s, off);
    if (l == 0) out[gw] = s + by[0];
}

// ---------------------------------------------------------------------------
// Launch order [pre, lstm, mu, zero]: zero at the END preps tags for the next
// graph replay (device globals are zero-init for the first call).
// ---------------------------------------------------------------------------
extern "C" void kernel_launch(void* const* d_in, const int* in_sizes, int n_in,
                              void* d_out, int out_size) {
    const float* x   = (const float*)d_in[0];
    const float* Wf  = (const float*)d_in[1];
    const float* Uf  = (const float*)d_in[2];
    const float* bf  = (const float*)d_in[3];
    const float* Wi  = (const float*)d_in[4];
    const float* Ui  = (const float*)d_in[5];
    const float* bi  = (const float*)d_in[6];
    const float* Wo  = (const float*)d_in[7];
    const float* Uo  = (const float*)d_in[8];
    const float* bo  = (const float*)d_in[9];
    const float* Wc  = (const float*)d_in[10];
    const float* Uc  = (const float*)d_in[11];
    const float* bc  = (const float*)d_in[12];
    const float* Ahy = (const float*)d_in[13];
    const float* by  = (const float*)d_in[14];
    float* out = (float*)d_out;

    precompute_kernel<<<dim3(STEPS / 64, NGC / 64), 256>>>(x, Wf, bf, Wi, bi, Wo, bo, Wc, bc);
    lstm_rec_kernel<<<NHD / 4, 192>>>(Uf, Ui, Uo, Uc);
    mu_kernel<<<(STEPS * 32 + 127) / 128, 128>>>(Ahy, by, out);
    zero_kernel<<<2048, 256>>>();
    (void)in_sizes; (void)n_in; (void)out_size;
}

// round 10
// speedup vs baseline: 3.9652x; 3.9652x over previous
#include <cuda_runtime.h>
#include <cstdint>

#define T_LEN 16384
#define NXD 128
#define NHD 512
#define STEPS (T_LEN - NXD)   /* 16256 */
#define NGC (NHD * 4)         /* 2048 */

// h history: per (t,j) one u64 = (tag = t+1) << 32 | float bits of h
__device__ unsigned long long g_h64[(size_t)STEPS * NHD];   // 66 MB
// gate pre-activations, interleaved (f,i,o,c) per (t,j)
__device__ float4 g_gate4[(size_t)STEPS * NHD];             // 133 MB

__device__ __forceinline__ unsigned long long ld_rlx(const unsigned long long* p) {
    unsigned long long v;
    asm volatile("ld.relaxed.gpu.global.u64 %0, [%1];" : "=l"(v) : "l"(p) : "memory");
    return v;
}
__device__ __forceinline__ void st_rlx(unsigned long long* p, unsigned long long v) {
    asm volatile("st.relaxed.gpu.global.u64 [%0], %1;" :: "l"(p), "l"(v) : "memory");
}
__device__ __forceinline__ float tanh_hw(float x) {
    float y;
    asm("tanh.approx.f32 %0, %1;" : "=f"(y) : "f"(x));
    return y;
}
__device__ __forceinline__ float sigm(float x) {
    return fmaf(tanh_hw(0.5f * x), 0.5f, 0.5f);
}
__device__ __forceinline__ float dot4(float4 a, float4 b) {
    return a.x * b.x + a.y * b.y + a.z * b.z + a.w * b.w;
}

// ---------------------------------------------------------------------------
// Clear tags (END of each call; device globals are zero-init for call 1)
// ---------------------------------------------------------------------------
__global__ void zero_kernel() {
    int idx = blockIdx.x * blockDim.x + threadIdx.x;
    int stride = gridDim.x * blockDim.x;
    for (int i = idx; i < STEPS * NHD; i += stride) g_h64[i] = 0ull;
}

// ---------------------------------------------------------------------------
// Gate pre-activation GEMM: gate[t][c] = b + sum_k W[c][k] * x[t+k]
// ---------------------------------------------------------------------------
__global__ void precompute_kernel(const float* __restrict__ x,
                                  const float* __restrict__ Wf, const float* __restrict__ bf,
                                  const float* __restrict__ Wi, const float* __restrict__ bi,
                                  const float* __restrict__ Wo, const float* __restrict__ bo,
                                  const float* __restrict__ Wc, const float* __restrict__ bc) {
    __shared__ float xs[192];
    __shared__ float Ws[128][65];
    const int tBase = blockIdx.x * 64;
    const int cBase = blockIdx.y * 64;
    const int tid = threadIdx.x;

    for (int i = tid; i < 191; i += 256) xs[i] = x[tBase + i];
    for (int idx = tid; idx < 8192; idx += 256) {
        int r = idx >> 7, k = idx & 127;
        int c = cBase + r;
        int j = c >> 2, g = c & 3;
        const float* W = (g == 0) ? Wf : (g == 1) ? Wi : (g == 2) ? Wo : Wc;
        Ws[k][r] = W[j * NXD + k];
    }
    __syncthreads();

    const int tx = tid & 15, ty = tid >> 4;
    const int t0 = ty * 4, r0 = tx * 4;
    float acc[4][4] = {};
#pragma unroll 4
    for (int k = 0; k < 128; k++) {
        float a0 = xs[t0 + 0 + k], a1 = xs[t0 + 1 + k];
        float a2 = xs[t0 + 2 + k], a3 = xs[t0 + 3 + k];
        float b0 = Ws[k][r0 + 0], b1 = Ws[k][r0 + 1];
        float b2 = Ws[k][r0 + 2], b3 = Ws[k][r0 + 3];
        acc[0][0] += a0 * b0; acc[0][1] += a0 * b1; acc[0][2] += a0 * b2; acc[0][3] += a0 * b3;
        acc[1][0] += a1 * b0; acc[1][1] += a1 * b1; acc[1][2] += a1 * b2; acc[1][3] += a1 * b3;
        acc[2][0] += a2 * b0; acc[2][1] += a2 * b1; acc[2][2] += a2 * b2; acc[2][3] += a2 * b3;
        acc[3][0] += a3 * b0; acc[3][1] += a3 * b1; acc[3][2] += a3 * b2; acc[3][3] += a3 * b3;
    }
    float* out = reinterpret_cast<float*>(g_gate4);
#pragma unroll
    for (int ti = 0; ti < 4; ti++) {
#pragma unroll
        for (int cj = 0; cj < 4; cj++) {
            int t = tBase + t0 + ti;
            int c = cBase + r0 + cj;
            int j = c >> 2, g = c & 3;
            float bias = (g == 0) ? bf[j] : (g == 1) ? bi[j] : (g == 2) ? bo[j] : bc[j];
            out[(size_t)t * NGC + c] = acc[ti][cj] + bias;
        }
    }
}

// ---------------------------------------------------------------------------
// Persistent self-synchronizing recurrence — EXACT R2 structure (the proven
// 19.5 ms shape) + ONE change: __nanosleep backoff between failed poll
// rounds. R2's stale-window polling generated ~8.5 KB/cyc of L2 demand
// (above the ~6.3 KB/cyc LTS cap), contending with the producer stores on
// the critical chain. The sleep parks the warp (no issue slots, no L2
// traffic) and cuts poll traffic ~2-3x below the cap.
// ---------------------------------------------------------------------------
__global__ void __launch_bounds__(128, 1)
lstm_rec_kernel(const float* __restrict__ Uf, const float* __restrict__ Ui,
                const float* __restrict__ Uo, const float* __restrict__ Uc) {
    __shared__ float hs[2][NHD];
    const int tid = threadIdx.x;
    const int w = tid >> 5, l = tid & 31;
    const int j = blockIdx.x * 4 + w;

    float4 u[4][4];
#pragma unroll
    for (int m = 0; m < 4; m++) {
        int off = j * NHD + m * 128 + l * 4;
        u[0][m] = *reinterpret_cast<const float4*>(Uf + off);
        u[1][m] = *reinterpret_cast<const float4*>(Ui + off);
        u[2][m] = *reinterpret_cast<const float4*>(Uo + off);
        u[3][m] = *reinterpret_cast<const float4*>(Uc + off);
    }

    float cst = 0.f;
    float4 gx = make_float4(0.f, 0.f, 0.f, 0.f);
    if (l == 0) gx = g_gate4[j];   // gate inputs for t = 0

    for (int t = 0; t < STEPS; t++) {
        float* hb = hs[t & 1];
        if (t == 0) {
#pragma unroll
            for (int q = 0; q < 4; q++) hb[tid + q * 128] = 0.f;
        } else {
            const unsigned long long* src = g_h64 + (size_t)(t - 1) * NHD;
            const unsigned tt = (unsigned)t;
            // issue all four polls back-to-back: 4 L2 round trips overlap
            unsigned long long v0 = ld_rlx(src + tid);
            unsigned long long v1 = ld_rlx(src + tid + 128);
            unsigned long long v2 = ld_rlx(src + tid + 256);
            unsigned long long v3 = ld_rlx(src + tid + 384);
            bool o0 = (unsigned)(v0 >> 32) == tt;
            bool o1 = (unsigned)(v1 >> 32) == tt;
            bool o2 = (unsigned)(v2 >> 32) == tt;
            bool o3 = (unsigned)(v3 >> 32) == tt;
            while (!(o0 && o1 && o2 && o3)) {
                __nanosleep(32);   // park warp: no issue slots, no L2 traffic
                if (!o0) { v0 = ld_rlx(src + tid);       o0 = (unsigned)(v0 >> 32) == tt; }
                if (!o1) { v1 = ld_rlx(src + tid + 128); o1 = (unsigned)(v1 >> 32) == tt; }
                if (!o2) { v2 = ld_rlx(src + tid + 256); o2 = (unsigned)(v2 >> 32) == tt; }
                if (!o3) { v3 = ld_rlx(src + tid + 384); o3 = (unsigned)(v3 >> 32) == tt; }
            }
            hb[tid]       = __uint_as_float((unsigned)v0);
            hb[tid + 128] = __uint_as_float((unsigned)v1);
            hb[tid + 256] = __uint_as_float((unsigned)v2);
            hb[tid + 384] = __uint_as_float((unsigned)v3);
        }
        __syncthreads();

        float4 h0 = *reinterpret_cast<float4*>(hb + 0   + l * 4);
        float4 h1 = *reinterpret_cast<float4*>(hb + 128 + l * 4);
        float4 h2 = *reinterpret_cast<float4*>(hb + 256 + l * 4);
        float4 h3 = *reinterpret_cast<float4*>(hb + 384 + l * 4);

        float a0 = dot4(u[0][0], h0) + dot4(u[0][1], h1) + dot4(u[0][2], h2) + dot4(u[0][3], h3);
        float a1 = dot4(u[1][0], h0) + dot4(u[1][1], h1) + dot4(u[1][2], h2) + dot4(u[1][3], h3);
        float a2 = dot4(u[2][0], h0) + dot4(u[2][1], h1) + dot4(u[2][2], h2) + dot4(u[2][3], h3);
        float a3 = dot4(u[3][0], h0) + dot4(u[3][1], h1) + dot4(u[3][2], h2) + dot4(u[3][3], h3);

#pragma unroll
        for (int off = 16; off; off >>= 1) {
            a0 += __shfl_down_sync(0xffffffffu, a0, off);
            a1 += __shfl_down_sync(0xffffffffu, a1, off);
            a2 += __shfl_down_sync(0xffffffffu, a2, off);
            a3 += __shfl_down_sync(0xffffffffu, a3, off);
        }

        if (l == 0) {
            float f = sigm(gx.x + a0);
            float i = sigm(gx.y + a1);
            float o = sigm(gx.z + a2);
            float g = tanh_hw(gx.w + a3);
            cst = f * cst + i * g;
            float h = o * tanh_hw(cst);
            st_rlx(g_h64 + (size_t)t * NHD + j,
                   ((unsigned long long)(unsigned)(t + 1) << 32) |
                   (unsigned long long)__float_as_uint(h));
            if (t + 1 < STEPS) gx = g_gate4[(size_t)(t + 1) * NHD + j];  // prefetch
        }
    }
}

// ---------------------------------------------------------------------------
// mu epilogue: out[t] = by + sum_j Ahy[j] * h[t][j]   (one warp per t)
// ---------------------------------------------------------------------------
__global__ void mu_kernel(const float* __restrict__ Ahy, const float* __restrict__ by,
                          float* __restrict__ out) {
    int gw = (int)((blockIdx.x * blockDim.x + threadIdx.x) >> 5);
    int l = threadIdx.x & 31;
    if (gw >= STEPS) return;
    const unsigned long long* hrow = g_h64 + (size_t)gw * NHD;
    float s = 0.f;
#pragma unroll
    for (int m = 0; m < 16; m++) {
        int idx = l + 32 * m;
        s += Ahy[idx] * __uint_as_float((unsigned)hrow[idx]);
    }
#pragma unroll
    for (int off = 16; off; off >>= 1) s += __shfl_down_sync(0xffffffffu, s, off);
    if (l == 0) out[gw] = s + by[0];
}

// ---------------------------------------------------------------------------
// Launch order [pre, lstm, mu, zero]: zero at the END preps tags for the next
// graph replay (device globals are zero-init for the first call).
// ---------------------------------------------------------------------------
extern "C" void kernel_launch(void* const* d_in, const int* in_sizes, int n_in,
                              void* d_out, int out_size) {
    const float* x   = (const float*)d_in[0];
    const float* Wf  = (const float*)d_in[1];
    const float* Uf  = (const float*)d_in[2];
    const float* bf  = (const float*)d_in[3];
    const float* Wi  = (const float*)d_in[4];
    const float* Ui  = (const float*)d_in[5];
    const float* bi  = (const float*)d_in[6];
    const float* Wo  = (const float*)d_in[7];
    const float* Uo  = (const float*)d_in[8];
    const float* bo  = (const float*)d_in[9];
    const float* Wc  = (const float*)d_in[10];
    const float* Uc  = (const float*)d_in[11];
    const float* bc  = (const float*)d_in[12];
    const float* Ahy = (const float*)d_in[13];
    const float* by  = (const float*)d_in[14];
    float* out = (float*)d_out;

    precompute_kernel<<<dim3(STEPS / 64, NGC / 64), 256>>>(x, Wf, bf, Wi, bi, Wo, bo, Wc, bc);
    lstm_rec_kernel<<<NHD / 4, 128>>>(Uf, Ui, Uo, Uc);
    mu_kernel<<<(STEPS * 32 + 127) / 128, 128>>>(Ahy, by, out);
    zero_kernel<<<2048, 256>>>();
    (void)in_sizes; (void)n_in; (void)out_size;
}

// round 11
// speedup vs baseline: 4.2272x; 1.0661x over previous
#include <cuda_runtime.h>
#include <cstdint>

#define T_LEN 16384
#define NXD 128
#define NHD 512
#define STEPS (T_LEN - NXD)   /* 16256 */
#define NGC (NHD * 4)         /* 2048 */

// h history: per (t,j) one u64 = (tag = t+1) << 32 | float bits of h
__device__ unsigned long long g_h64[(size_t)STEPS * NHD];   // 66 MB
// gate pre-activations, interleaved (f,i,o,c) per (t,j)
__device__ float4 g_gate4[(size_t)STEPS * NHD];             // 133 MB

__device__ __forceinline__ unsigned long long ld_rlx(const unsigned long long* p) {
    unsigned long long v;
    asm volatile("ld.relaxed.gpu.global.u64 %0, [%1];" : "=l"(v) : "l"(p) : "memory");
    return v;
}
__device__ __forceinline__ void st_rlx(unsigned long long* p, unsigned long long v) {
    asm volatile("st.relaxed.gpu.global.u64 [%0], %1;" :: "l"(p), "l"(v) : "memory");
}
__device__ __forceinline__ float tanh_hw(float x) {
    float y;
    asm("tanh.approx.f32 %0, %1;" : "=f"(y) : "f"(x));
    return y;
}
__device__ __forceinline__ float sigm(float x) {
    return fmaf(tanh_hw(0.5f * x), 0.5f, 0.5f);
}
__device__ __forceinline__ unsigned long long pack2(float lo, float hi) {
    unsigned long long r;
    asm("mov.b64 %0, {%1, %2};" : "=l"(r) : "f"(lo), "f"(hi));
    return r;
}
__device__ __forceinline__ void fma2(unsigned long long& d,
                                     unsigned long long a, unsigned long long b) {
    asm("fma.rn.f32x2 %0, %1, %2, %0;" : "+l"(d) : "l"(a), "l"(b));
}
__device__ __forceinline__ float hsum2(unsigned long long v) {
    float lo, hi;
    asm("mov.b64 {%0, %1}, %2;" : "=f"(lo), "=f"(hi) : "l"(v));
    return lo + hi;
}

// ---------------------------------------------------------------------------
// Clear tags (END of each call; device globals are zero-init for call 1)
// ---------------------------------------------------------------------------
__global__ void zero_kernel() {
    int idx = blockIdx.x * blockDim.x + threadIdx.x;
    int stride = gridDim.x * blockDim.x;
    for (int i = idx; i < STEPS * NHD; i += stride) g_h64[i] = 0ull;
}

// ---------------------------------------------------------------------------
// Gate pre-activation GEMM: gate[t][c] = b + sum_k W[c][k] * x[t+k]
// ---------------------------------------------------------------------------
__global__ void precompute_kernel(const float* __restrict__ x,
                                  const float* __restrict__ Wf, const float* __restrict__ bf,
                                  const float* __restrict__ Wi, const float* __restrict__ bi,
                                  const float* __restrict__ Wo, const float* __restrict__ bo,
                                  const float* __restrict__ Wc, const float* __restrict__ bc) {
    __shared__ float xs[192];
    __shared__ float Ws[128][65];
    const int tBase = blockIdx.x * 64;
    const int cBase = blockIdx.y * 64;
    const int tid = threadIdx.x;

    for (int i = tid; i < 191; i += 256) xs[i] = x[tBase + i];
    for (int idx = tid; idx < 8192; idx += 256) {
        int r = idx >> 7, k = idx & 127;
        int c = cBase + r;
        int j = c >> 2, g = c & 3;
        const float* W = (g == 0) ? Wf : (g == 1) ? Wi : (g == 2) ? Wo : Wc;
        Ws[k][r] = W[j * NXD + k];
    }
    __syncthreads();

    const int tx = tid & 15, ty = tid >> 4;
    const int t0 = ty * 4, r0 = tx * 4;
    float acc[4][4] = {};
#pragma unroll 4
    for (int k = 0; k < 128; k++) {
        float a0 = xs[t0 + 0 + k], a1 = xs[t0 + 1 + k];
        float a2 = xs[t0 + 2 + k], a3 = xs[t0 + 3 + k];
        float b0 = Ws[k][r0 + 0], b1 = Ws[k][r0 + 1];
        float b2 = Ws[k][r0 + 2], b3 = Ws[k][r0 + 3];
        acc[0][0] += a0 * b0; acc[0][1] += a0 * b1; acc[0][2] += a0 * b2; acc[0][3] += a0 * b3;
        acc[1][0] += a1 * b0; acc[1][1] += a1 * b1; acc[1][2] += a1 * b2; acc[1][3] += a1 * b3;
        acc[2][0] += a2 * b0; acc[2][1] += a2 * b1; acc[2][2] += a2 * b2; acc[2][3] += a2 * b3;
        acc[3][0] += a3 * b0; acc[3][1] += a3 * b1; acc[3][2] += a3 * b2; acc[3][3] += a3 * b3;
    }
    float* out = reinterpret_cast<float*>(g_gate4);
#pragma unroll
    for (int ti = 0; ti < 4; ti++) {
#pragma unroll
        for (int cj = 0; cj < 4; cj++) {
            int t = tBase + t0 + ti;
            int c = cBase + r0 + cj;
            int j = c >> 2, g = c & 3;
            float bias = (g == 0) ? bf[j] : (g == 1) ? bi[j] : (g == 2) ? bo[j] : bc[j];
            out[(size_t)t * NGC + c] = acc[ti][cj] + bias;
        }
    }
}

// ---------------------------------------------------------------------------
// Persistent self-synchronizing recurrence — EXACT R2 exchange (proven best:
// strided tagged u64, 4 overlapped polls, immediate retry, one barrier,
// lane-0 epilogue). ONE change vs R2: the per-lane dot products use packed
// fma.rn.f32x2 (FFMA2) — 32 packed FMAs instead of 64 FFMA on the serial
// chain. Same fp32 arithmetic, same traffic, same sync.
// ---------------------------------------------------------------------------
__global__ void __launch_bounds__(128, 1)
lstm_rec_kernel(const float* __restrict__ Uf, const float* __restrict__ Ui,
                const float* __restrict__ Uo, const float* __restrict__ Uc) {
    __shared__ float hs[2][NHD];
    const int tid = threadIdx.x;
    const int w = tid >> 5, l = tid & 31;
    const int j = blockIdx.x * 4 + w;

    // U rows packed as f32 pairs: u2[g][m*2+p] covers h[m*128 + l*4 + 2p .. +1]
    unsigned long long u2[4][8];
    {
        const float* Us[4] = {Uf, Ui, Uo, Uc};
#pragma unroll
        for (int g = 0; g < 4; g++) {
#pragma unroll
            for (int m = 0; m < 4; m++) {
                float4 q = *reinterpret_cast<const float4*>(Us[g] + j * NHD + m * 128 + l * 4);
                u2[g][m * 2 + 0] = pack2(q.x, q.y);
                u2[g][m * 2 + 1] = pack2(q.z, q.w);
            }
        }
    }

    float cst = 0.f;
    float4 gx = make_float4(0.f, 0.f, 0.f, 0.f);
    if (l == 0) gx = g_gate4[j];   // gate inputs for t = 0

    for (int t = 0; t < STEPS; t++) {
        float* hb = hs[t & 1];
        if (t == 0) {
#pragma unroll
            for (int q = 0; q < 4; q++) hb[tid + q * 128] = 0.f;
        } else {
            const unsigned long long* src = g_h64 + (size_t)(t - 1) * NHD;
            const unsigned tt = (unsigned)t;
            // issue all four polls back-to-back: 4 L2 round trips overlap
            unsigned long long v0 = ld_rlx(src + tid);
            unsigned long long v1 = ld_rlx(src + tid + 128);
            unsigned long long v2 = ld_rlx(src + tid + 256);
            unsigned long long v3 = ld_rlx(src + tid + 384);
            bool o0 = (unsigned)(v0 >> 32) == tt;
            bool o1 = (unsigned)(v1 >> 32) == tt;
            bool o2 = (unsigned)(v2 >> 32) == tt;
            bool o3 = (unsigned)(v3 >> 32) == tt;
            while (!(o0 && o1 && o2 && o3)) {
                if (!o0) { v0 = ld_rlx(src + tid);       o0 = (unsigned)(v0 >> 32) == tt; }
                if (!o1) { v1 = ld_rlx(src + tid + 128); o1 = (unsigned)(v1 >> 32) == tt; }
                if (!o2) { v2 = ld_rlx(src + tid + 256); o2 = (unsigned)(v2 >> 32) == tt; }
                if (!o3) { v3 = ld_rlx(src + tid + 384); o3 = (unsigned)(v3 >> 32) == tt; }
            }
            hb[tid]       = __uint_as_float((unsigned)v0);
            hb[tid + 128] = __uint_as_float((unsigned)v1);
            hb[tid + 256] = __uint_as_float((unsigned)v2);
            hb[tid + 384] = __uint_as_float((unsigned)v3);
        }
        __syncthreads();

        // packed h slices (16B smem loads, bit-identical reinterpret)
        const ulonglong2 hp0 = *reinterpret_cast<const ulonglong2*>(hb + 0   + l * 4);
        const ulonglong2 hp1 = *reinterpret_cast<const ulonglong2*>(hb + 128 + l * 4);
        const ulonglong2 hp2 = *reinterpret_cast<const ulonglong2*>(hb + 256 + l * 4);
        const ulonglong2 hp3 = *reinterpret_cast<const ulonglong2*>(hb + 384 + l * 4);

        float a0, a1, a2, a3;
        {
            unsigned long long c0 = 0ull, c1 = 0ull, c2 = 0ull, c3 = 0ull;
            fma2(c0, u2[0][0], hp0.x); fma2(c1, u2[1][0], hp0.x);
            fma2(c2, u2[2][0], hp0.x); fma2(c3, u2[3][0], hp0.x);
            fma2(c0, u2[0][1], hp0.y); fma2(c1, u2[1][1], hp0.y);
            fma2(c2, u2[2][1], hp0.y); fma2(c3, u2[3][1], hp0.y);
            fma2(c0, u2[0][2], hp1.x); fma2(c1, u2[1][2], hp1.x);
            fma2(c2, u2[2][2], hp1.x); fma2(c3, u2[3][2], hp1.x);
            fma2(c0, u2[0][3], hp1.y); fma2(c1, u2[1][3], hp1.y);
            fma2(c2, u2[2][3], hp1.y); fma2(c3, u2[3][3], hp1.y);
            fma2(c0, u2[0][4], hp2.x); fma2(c1, u2[1][4], hp2.x);
            fma2(c2, u2[2][4], hp2.x); fma2(c3, u2[3][4], hp2.x);
            fma2(c0, u2[0][5], hp2.y); fma2(c1, u2[1][5], hp2.y);
            fma2(c2, u2[2][5], hp2.y); fma2(c3, u2[3][5], hp2.y);
            fma2(c0, u2[0][6], hp3.x); fma2(c1, u2[1][6], hp3.x);
            fma2(c2, u2[2][6], hp3.x); fma2(c3, u2[3][6], hp3.x);
            fma2(c0, u2[0][7], hp3.y); fma2(c1, u2[1][7], hp3.y);
            fma2(c2, u2[2][7], hp3.y); fma2(c3, u2[3][7], hp3.y);
            a0 = hsum2(c0); a1 = hsum2(c1); a2 = hsum2(c2); a3 = hsum2(c3);
        }

#pragma unroll
        for (int off = 16; off; off >>= 1) {
            a0 += __shfl_down_sync(0xffffffffu, a0, off);
            a1 += __shfl_down_sync(0xffffffffu, a1, off);
            a2 += __shfl_down_sync(0xffffffffu, a2, off);
            a3 += __shfl_down_sync(0xffffffffu, a3, off);
        }

        if (l == 0) {
            float f = sigm(gx.x + a0);
            float i = sigm(gx.y + a1);
            float o = sigm(gx.z + a2);
            float g = tanh_hw(gx.w + a3);
            cst = f * cst + i * g;
            float h = o * tanh_hw(cst);
            st_rlx(g_h64 + (size_t)t * NHD + j,
                   ((unsigned long long)(unsigned)(t + 1) << 32) |
                   (unsigned long long)__float_as_uint(h));
            if (t + 1 < STEPS) gx = g_gate4[(size_t)(t + 1) * NHD + j];  // prefetch
        }
    }
}

// ---------------------------------------------------------------------------
// mu epilogue: out[t] = by + sum_j Ahy[j] * h[t][j]   (one warp per t)
// ---------------------------------------------------------------------------
__global__ void mu_kernel(const float* __restrict__ Ahy, const float* __restrict__ by,
                          float* __restrict__ out) {
    int gw = (int)((blockIdx.x * blockDim.x + threadIdx.x) >> 5);
    int l = threadIdx.x & 31;
    if (gw >= STEPS) return;
    const unsigned long long* hrow = g_h64 + (size_t)gw * NHD;
    float s = 0.f;
#pragma unroll
    for (int m = 0; m < 16; m++) {
        int idx = l + 32 * m;
        s += Ahy[idx] * __uint_as_float((unsigned)hrow[idx]);
    }
#pragma unroll
    for (int off = 16; off; off >>= 1) s += __shfl_down_sync(0xffffffffu, s, off);
    if (l == 0) out[gw] = s + by[0];
}

// ---------------------------------------------------------------------------
// Launch order [pre, lstm, mu, zero]: zero at the END preps tags for the next
// graph replay (device globals are zero-init for the first call).
// ---------------------------------------------------------------------------
extern "C" void kernel_launch(void* const* d_in, const int* in_sizes, int n_in,
                              void* d_out, int out_size) {
    const float* x   = (const float*)d_in[0];
    const float* Wf  = (const float*)d_in[1];
    const float* Uf  = (const float*)d_in[2];
    const float* bf  = (const float*)d_in[3];
    const float* Wi  = (const float*)d_in[4];
    const float* Ui  = (const float*)d_in[5];
    const float* bi  = (const float*)d_in[6];
    const float* Wo  = (const float*)d_in[7];
    const float* Uo  = (const float*)d_in[8];
    const float* bo  = (const float*)d_in[9];
    const float* Wc  = (const float*)d_in[10];
    const float* Uc  = (const float*)d_in[11];
    const float* bc  = (const float*)d_in[12];
    const float* Ahy = (const float*)d_in[13];
    const float* by  = (const float*)d_in[14];
    float* out = (float*)d_out;

    precompute_kernel<<<dim3(STEPS / 64, NGC / 64), 256>>>(x, Wf, bf, Wi, bi, Wo, bo, Wc, bc);
    lstm_rec_kernel<<<NHD / 4, 128>>>(Uf, Ui, Uo, Uc);
    mu_kernel<<<(STEPS * 32 + 127) / 128, 128>>>(Ahy, by, out);
    zero_kernel<<<2048, 256>>>();
    (void)in_sizes; (void)n_in; (void)out_size;
}